// round 1
// baseline (speedup 1.0000x reference)
#include <cuda_runtime.h>
#include <cuda_bf16.h>
#include <float.h>

#define B_IMG 2
#define N_BOX 20000
#define C_CLS 80
#define BC (B_IMG * C_CLS)
#define CAP 2048            // per-(b,c) candidate capacity (mean ~400, 80+ sigma headroom)
#define PRE_K 1000
#define MAX_DET 300
#define SCORE_THR 0.05f
#define IOU_THR 0.5f

// ---------------- scratch (no allocations allowed) ----------------
__device__ int   g_cand_count[BC];
__device__ float g_cand_score[BC * CAP];
__device__ int   g_cand_idx[BC * CAP];
__device__ int   g_keep_count[BC];
__device__ float g_keep_score[BC * MAX_DET];
__device__ int   g_keep_idx[BC * MAX_DET];

// ---------------- K0: zero counters ----------------
__global__ void zero_kernel() {
    int t = threadIdx.x;
    if (t < BC) g_cand_count[t] = 0;
}

// ---------------- K1: threshold + compact ----------------
__global__ void compact_kernel(const float* __restrict__ cls,
                               const float* __restrict__ cen) {
    int e = blockIdx.x * blockDim.x + threadIdx.x;
    if (e >= B_IMG * N_BOX * C_CLS) return;
    float raw = cls[e];
    if (raw > SCORE_THR) {
        int c = e % C_CLS;
        int n = (e / C_CLS) % N_BOX;
        int b = e / (N_BOX * C_CLS);
        float s = sqrtf(raw * cen[b * N_BOX + n]);   // comb score
        int bc = b * C_CLS + c;
        int pos = atomicAdd(&g_cand_count[bc], 1);
        if (pos < CAP) {
            g_cand_score[bc * CAP + pos] = s;
            g_cand_idx[bc * CAP + pos]   = n;
        }
    }
}

// ---------------- K2: per-(b,c) sort + greedy NMS ----------------
__global__ __launch_bounds__(256) void sort_nms_kernel(const float* __restrict__ boxes) {
    __shared__ float s_score[CAP];
    __shared__ int   s_idx[CAP];
    __shared__ float s_x1[PRE_K], s_y1[PRE_K], s_x2[PRE_K], s_y2[PRE_K], s_area[PRE_K];
    __shared__ unsigned char s_sup[PRE_K];
    __shared__ int s_nkept;

    const int bc = blockIdx.x;
    const int b  = bc / C_CLS;
    const int tid = threadIdx.x;
    const int bd  = blockDim.x;

    int V = g_cand_count[bc];
    if (V > CAP) V = CAP;

    // next pow2 >= V (>=1)
    int M = 1;
    while (M < V) M <<= 1;

    for (int i = tid; i < M; i += bd) {
        if (i < V) {
            s_score[i] = g_cand_score[bc * CAP + i];
            s_idx[i]   = g_cand_idx[bc * CAP + i];
        } else {
            s_score[i] = -FLT_MAX;
            s_idx[i]   = 0x7fffffff;
        }
    }
    __syncthreads();

    // bitonic sort, descending by score, ties -> smaller original index first
    for (int k = 2; k <= M; k <<= 1) {
        for (int j = k >> 1; j > 0; j >>= 1) {
            for (int i = tid; i < M; i += bd) {
                int ixj = i ^ j;
                if (ixj > i) {
                    float si = s_score[i], sj = s_score[ixj];
                    int ii = s_idx[i], ij = s_idx[ixj];
                    bool i_first = (si > sj) || (si == sj && ii < ij);
                    bool up = ((i & k) == 0);         // descending segment
                    bool do_swap = up ? !i_first : i_first;
                    if (do_swap) {
                        s_score[i] = sj; s_score[ixj] = si;
                        s_idx[i]   = ij; s_idx[ixj]   = ii;
                    }
                }
            }
            __syncthreads();
        }
    }

    int K_eff = V < PRE_K ? V : PRE_K;

    // gather candidate boxes into smem
    for (int i = tid; i < K_eff; i += bd) {
        int n = s_idx[i];
        float4 bb = reinterpret_cast<const float4*>(boxes)[b * N_BOX + n];
        s_x1[i] = bb.x; s_y1[i] = bb.y; s_x2[i] = bb.z; s_y2[i] = bb.w;
        s_area[i] = (bb.z - bb.x) * (bb.w - bb.y);
        s_sup[i] = 0;
    }
    if (tid == 0) s_nkept = 0;
    __syncthreads();

    // greedy NMS: barrier only when a box is actually kept
    for (int i = 0; i < K_eff; i++) {
        if (!s_sup[i]) {
            if (tid == 0) {
                int nk = s_nkept;
                g_keep_score[bc * MAX_DET + nk] = s_score[i];
                g_keep_idx[bc * MAX_DET + nk]   = s_idx[i];
                s_nkept = nk + 1;
            }
            float xi1 = s_x1[i], yi1 = s_y1[i], xi2 = s_x2[i], yi2 = s_y2[i], ai = s_area[i];
            for (int j = i + 1 + tid; j < K_eff; j += bd) {
                if (!s_sup[j]) {
                    float ltx = fmaxf(xi1, s_x1[j]);
                    float lty = fmaxf(yi1, s_y1[j]);
                    float rbx = fminf(xi2, s_x2[j]);
                    float rby = fminf(yi2, s_y2[j]);
                    float w = fmaxf(rbx - ltx, 0.0f);
                    float h = fmaxf(rby - lty, 0.0f);
                    float inter = w * h;
                    float uni = ai + s_area[j] - inter;
                    float iou = inter / fmaxf(uni, 1e-8f);
                    if (iou > IOU_THR) s_sup[j] = 1;
                }
            }
            __syncthreads();
            if (s_nkept >= MAX_DET) break;
        }
    }
    if (tid == 0) g_keep_count[bc] = (s_nkept <= MAX_DET) ? s_nkept : MAX_DET;
}

// ---------------- K3: per-image 80-way sorted merge, top-300 ----------------
__global__ void merge_kernel(const float* __restrict__ boxes, float* __restrict__ out) {
    __shared__ int head[C_CLS];
    const int b = blockIdx.x;
    const int lane = threadIdx.x;   // 32 threads

    for (int c = lane; c < C_CLS; c += 32) head[c] = 0;
    __syncwarp();

    for (int t = 0; t < MAX_DET; t++) {
        float best = -1.0f;
        int bestc = 1 << 20;
        for (int c = lane; c < C_CLS; c += 32) {
            int h = head[c];
            if (h < g_keep_count[b * C_CLS + c]) {
                float s = g_keep_score[(b * C_CLS + c) * MAX_DET + h];
                if (s > best || (s == best && c < bestc)) { best = s; bestc = c; }
            }
        }
        // warp argmax reduce (tie -> smaller class, matches flat top_k order)
        for (int off = 16; off; off >>= 1) {
            float ob = __shfl_down_sync(0xffffffff, best, off);
            int   oc = __shfl_down_sync(0xffffffff, bestc, off);
            if (ob > best || (ob == best && oc < bestc)) { best = ob; bestc = oc; }
        }
        best  = __shfl_sync(0xffffffff, best, 0);
        bestc = __shfl_sync(0xffffffff, bestc, 0);

        if (lane == 0) {
            float* fb = out + b * (MAX_DET * 4) + t * 4;
            float* fs = out + B_IMG * MAX_DET * 4 + b * MAX_DET + t;
            float* fl = out + B_IMG * MAX_DET * 4 + B_IMG * MAX_DET + b * MAX_DET + t;
            if (best > 0.0f) {
                int h = head[bestc];
                int n = g_keep_idx[(b * C_CLS + bestc) * MAX_DET + h];
                head[bestc] = h + 1;
                float4 bb = reinterpret_cast<const float4*>(boxes)[b * N_BOX + n];
                fb[0] = bb.x; fb[1] = bb.y; fb[2] = bb.z; fb[3] = bb.w;
                *fs = best;
                *fl = (float)bestc;
            } else {
                fb[0] = -1.0f; fb[1] = -1.0f; fb[2] = -1.0f; fb[3] = -1.0f;
                *fs = -1.0f;
                *fl = -1.0f;
            }
        }
        __syncwarp();
    }
}

// ---------------- host launcher ----------------
extern "C" void kernel_launch(void* const* d_in, const int* in_sizes, int n_in,
                              void* d_out, int out_size) {
    const float* boxes = (const float*)d_in[0];           // [2,20000,4]
    const float* cls   = (const float*)d_in[1];           // [2,20000,80]
    const float* cen   = (const float*)d_in[2];           // [2,20000,1]
    float* out = (float*)d_out;                           // fb(2400) | fs(600) | fl(600)

    zero_kernel<<<1, 256>>>();
    int total = B_IMG * N_BOX * C_CLS;
    compact_kernel<<<(total + 255) / 256, 256>>>(cls, cen);
    sort_nms_kernel<<<BC, 256>>>(boxes);
    merge_kernel<<<B_IMG, 32>>>(boxes, out);
}

// round 2
// speedup vs baseline: 1.2477x; 1.2477x over previous
#include <cuda_runtime.h>
#include <float.h>

#define B_IMG 2
#define N_BOX 20000
#define C_CLS 80
#define BC (B_IMG * C_CLS)
#define CAP 1024            // candidate capacity per (b,c); mean ~400, sigma ~20 -> 31 sigma headroom
#define PRE_K 1000
#define MAXV 640            // fast-path limit (12 sigma); beyond -> slow fallback (correct, never taken)
#define WMAX ((MAXV + 31) / 32)   // 20
#define MAX_DET 300
#define SCORE_THR 0.05f
#define IOU_THR 0.5f
#define WIN 64              // merge staging window per class (max consumption ~15)

// ---------------- scratch (no allocations allowed) ----------------
__device__ int   g_cand_count[BC];
__device__ float g_cand_score[BC * CAP];
__device__ int   g_cand_idx[BC * CAP];
__device__ int   g_keep_count[BC];
__device__ float g_keep_score[BC * MAX_DET];
__device__ int   g_keep_idx[BC * MAX_DET];

// ---------------- K0: zero counters ----------------
__global__ void zero_kernel() {
    int t = threadIdx.x;
    if (t < BC) g_cand_count[t] = 0;
}

// ---------------- K1: threshold + compact (float4 reads) ----------------
__global__ void compact_kernel(const float4* __restrict__ cls4,
                               const float* __restrict__ cen) {
    int q = blockIdx.x * blockDim.x + threadIdx.x;
    const int total4 = B_IMG * N_BOX * C_CLS / 4;
    if (q >= total4) return;
    float4 v = cls4[q];
    float vv[4] = {v.x, v.y, v.z, v.w};
    int base = q * 4;
    #pragma unroll
    for (int k = 0; k < 4; k++) {
        float raw = vv[k];
        if (raw > SCORE_THR) {
            int e = base + k;
            int c = e % C_CLS;
            int n = (e / C_CLS) % N_BOX;
            int b = e / (N_BOX * C_CLS);
            float s = sqrtf(raw * cen[b * N_BOX + n]);
            int bc = b * C_CLS + c;
            int pos = atomicAdd(&g_cand_count[bc], 1);
            if (pos < CAP) {
                g_cand_score[bc * CAP + pos] = s;
                g_cand_idx[bc * CAP + pos]   = n;
            }
        }
    }
}

// ---------------- K2: per-(b,c) sort + bitmask NMS ----------------
__global__ __launch_bounds__(256) void sort_nms_kernel(const float* __restrict__ boxes) {
    extern __shared__ unsigned char dynbuf[];
    float*    s_score = (float*)dynbuf;                 // CAP
    int*      s_idx   = (int*)(s_score + CAP);          // CAP
    float*    s_x1 = (float*)(s_idx + CAP);             // MAXV
    float*    s_y1 = s_x1 + MAXV;
    float*    s_x2 = s_y1 + MAXV;
    float*    s_y2 = s_x2 + MAXV;
    float*    s_ar = s_y2 + MAXV;
    unsigned* s_mask = (unsigned*)(s_ar + MAXV);        // MAXV * WMAX

    const int bc  = blockIdx.x;
    const int b   = bc / C_CLS;
    const int tid = threadIdx.x;
    const int bd  = blockDim.x;

    int V = g_cand_count[bc];
    if (V > CAP) V = CAP;
    int M = 1;
    while (M < V) M <<= 1;

    for (int i = tid; i < M; i += bd) {
        if (i < V) {
            s_score[i] = g_cand_score[bc * CAP + i];
            s_idx[i]   = g_cand_idx[bc * CAP + i];
        } else {
            s_score[i] = -FLT_MAX;
            s_idx[i]   = 0x7fffffff;
        }
    }
    __syncthreads();

    // bitonic sort: score desc, tie -> smaller original index
    for (int k = 2; k <= M; k <<= 1) {
        for (int j = k >> 1; j > 0; j >>= 1) {
            for (int i = tid; i < M; i += bd) {
                int ixj = i ^ j;
                if (ixj > i) {
                    float si = s_score[i], sj = s_score[ixj];
                    int ii = s_idx[i], ij = s_idx[ixj];
                    bool i_first = (si > sj) || (si == sj && ii < ij);
                    bool up = ((i & k) == 0);
                    if (up ? !i_first : i_first) {
                        s_score[i] = sj; s_score[ixj] = si;
                        s_idx[i]   = ij; s_idx[ixj]   = ii;
                    }
                }
            }
            __syncthreads();
        }
    }

    int K_eff = V < PRE_K ? V : PRE_K;

    if (V <= MAXV) {
        // -------- fast path: bitmask NMS --------
        for (int i = tid; i < K_eff; i += bd) {
            float4 bb = reinterpret_cast<const float4*>(boxes)[b * N_BOX + s_idx[i]];
            s_x1[i] = bb.x; s_y1[i] = bb.y; s_x2[i] = bb.z; s_y2[i] = bb.w;
            s_ar[i] = (bb.z - bb.x) * (bb.w - bb.y);
        }
        __syncthreads();

        int W = (K_eff + 31) >> 5;
        for (int t = tid; t < K_eff * W; t += bd) {
            int i = t / W, w = t % W;
            unsigned m = 0;
            int jb = w << 5;
            if (jb + 31 > i) {
                float xi1 = s_x1[i], yi1 = s_y1[i], xi2 = s_x2[i], yi2 = s_y2[i], ai = s_ar[i];
                int jend = min(jb + 32, K_eff);
                for (int j = max(jb, i + 1); j < jend; j++) {
                    float w_ = fmaxf(fminf(xi2, s_x2[j]) - fmaxf(xi1, s_x1[j]), 0.0f);
                    float h_ = fmaxf(fminf(yi2, s_y2[j]) - fmaxf(yi1, s_y1[j]), 0.0f);
                    float inter = w_ * h_;
                    float uni = ai + s_ar[j] - inter;
                    if (inter / fmaxf(uni, 1e-8f) > IOU_THR) m |= 1u << (j - jb);
                }
            }
            s_mask[t] = m;
        }
        __syncthreads();

        if (tid < 32) {
            unsigned sup = 0;   // lane l owns suppressed bits for candidates [32l, 32l+32)
            int nk = 0;
            for (int i = 0; i < K_eff && nk < MAX_DET; i++) {
                unsigned ow = __shfl_sync(0xffffffffu, sup, i >> 5);
                if (!(ow & (1u << (i & 31)))) {
                    if (tid == 0) {
                        g_keep_score[bc * MAX_DET + nk] = s_score[i];
                        g_keep_idx[bc * MAX_DET + nk]   = s_idx[i];
                    }
                    if (tid < W) sup |= s_mask[i * W + tid];
                    nk++;
                }
            }
            if (tid == 0) g_keep_count[bc] = nk;
        }
    } else {
        // -------- slow fallback (barrier greedy, boxes from global) --------
        unsigned char* sup = (unsigned char*)s_mask;
        __shared__ int s_nk;
        for (int i = tid; i < K_eff; i += bd) sup[i] = 0;
        if (tid == 0) s_nk = 0;
        __syncthreads();
        for (int i = 0; i < K_eff; i++) {
            if (!sup[i]) {
                if (tid == 0) {
                    int nk = s_nk;
                    g_keep_score[bc * MAX_DET + nk] = s_score[i];
                    g_keep_idx[bc * MAX_DET + nk]   = s_idx[i];
                    s_nk = nk + 1;
                }
                float4 bi = reinterpret_cast<const float4*>(boxes)[b * N_BOX + s_idx[i]];
                float ai = (bi.z - bi.x) * (bi.w - bi.y);
                for (int j = i + 1 + tid; j < K_eff; j += bd) {
                    if (!sup[j]) {
                        float4 bj = reinterpret_cast<const float4*>(boxes)[b * N_BOX + s_idx[j]];
                        float aj = (bj.z - bj.x) * (bj.w - bj.y);
                        float w_ = fmaxf(fminf(bi.z, bj.z) - fmaxf(bi.x, bj.x), 0.0f);
                        float h_ = fmaxf(fminf(bi.w, bj.w) - fmaxf(bi.y, bj.y), 0.0f);
                        float inter = w_ * h_;
                        float uni = ai + aj - inter;
                        if (inter / fmaxf(uni, 1e-8f) > IOU_THR) sup[j] = 1;
                    }
                }
                __syncthreads();
                if (s_nk >= MAX_DET) break;
            }
        }
        if (tid == 0) g_keep_count[bc] = (s_nk <= MAX_DET) ? s_nk : MAX_DET;
    }
}

// ---------------- K3: per-image 80-way merge, SMEM-staged, cached heads ----------------
__global__ __launch_bounds__(512) void merge_kernel(const float* __restrict__ boxes,
                                                    float* __restrict__ out) {
    __shared__ float s_sc[C_CLS * WIN];
    __shared__ int   s_ix[C_CLS * WIN];
    __shared__ int   s_cnt[C_CLS];
    __shared__ float s_sel_s[MAX_DET];
    __shared__ int   s_sel_c[MAX_DET];
    __shared__ int   s_sel_i[MAX_DET];

    const int b   = blockIdx.x;
    const int tid = threadIdx.x;

    if (tid < C_CLS) s_cnt[tid] = g_keep_count[b * C_CLS + tid];
    for (int t = tid; t < MAX_DET; t += blockDim.x) {
        s_sel_s[t] = -1.0f; s_sel_c[t] = -1; s_sel_i[t] = 0;
    }
    __syncthreads();

    for (int t = tid; t < C_CLS * WIN; t += blockDim.x) {
        int c = t / WIN, r = t % WIN;
        bool ok = r < s_cnt[c];
        s_sc[t] = ok ? g_keep_score[(b * C_CLS + c) * MAX_DET + r] : -1.0f;
        s_ix[t] = ok ? g_keep_idx[(b * C_CLS + c) * MAX_DET + r]   : 0;
    }
    __syncthreads();

    if (tid < 32) {
        const int lane = tid;
        const int c0 = lane, c1 = lane + 32, c2 = lane + 64;
        int n0 = s_cnt[c0], n1 = s_cnt[c1], n2 = (c2 < C_CLS) ? s_cnt[c2] : 0;
        int h0 = 0, h1 = 0, h2 = 0;
        float f0 = (n0 > 0) ? s_sc[c0 * WIN] : -1.0f;
        float f1 = (n1 > 0) ? s_sc[c1 * WIN] : -1.0f;
        float f2 = (n2 > 0) ? s_sc[c2 * WIN] : -1.0f;

        for (int t = 0; t < MAX_DET; t++) {
            float bs = f0; int bcl = c0;
            if (f1 > bs) { bs = f1; bcl = c1; }
            if (f2 > bs) { bs = f2; bcl = c2; }
            #pragma unroll
            for (int off = 16; off; off >>= 1) {
                float os = __shfl_xor_sync(0xffffffffu, bs, off);
                int   oc = __shfl_xor_sync(0xffffffffu, bcl, off);
                if (os > bs || (os == bs && oc < bcl)) { bs = os; bcl = oc; }
            }
            if (bs <= 0.0f) break;
            if (lane == (bcl & 31)) {
                int gbase = (b * C_CLS + bcl) * MAX_DET;
                s_sel_s[t] = bs; s_sel_c[t] = bcl;
                if (bcl < 32) {
                    s_sel_i[t] = (h0 < WIN) ? s_ix[bcl * WIN + h0] : g_keep_idx[gbase + h0];
                    h0++;
                    f0 = (h0 < n0) ? ((h0 < WIN) ? s_sc[bcl * WIN + h0] : g_keep_score[gbase + h0]) : -1.0f;
                } else if (bcl < 64) {
                    s_sel_i[t] = (h1 < WIN) ? s_ix[bcl * WIN + h1] : g_keep_idx[gbase + h1];
                    h1++;
                    f1 = (h1 < n1) ? ((h1 < WIN) ? s_sc[bcl * WIN + h1] : g_keep_score[gbase + h1]) : -1.0f;
                } else {
                    s_sel_i[t] = (h2 < WIN) ? s_ix[bcl * WIN + h2] : g_keep_idx[gbase + h2];
                    h2++;
                    f2 = (h2 < n2) ? ((h2 < WIN) ? s_sc[bcl * WIN + h2] : g_keep_score[gbase + h2]) : -1.0f;
                }
            }
        }
    }
    __syncthreads();

    if (tid < MAX_DET) {
        float sc = s_sel_s[tid];
        float* fb = out + b * (MAX_DET * 4) + tid * 4;
        float* fs = out + B_IMG * MAX_DET * 4 + b * MAX_DET + tid;
        float* fl = out + B_IMG * MAX_DET * 4 + B_IMG * MAX_DET + b * MAX_DET + tid;
        if (sc > 0.0f) {
            float4 bb = reinterpret_cast<const float4*>(boxes)[b * N_BOX + s_sel_i[tid]];
            fb[0] = bb.x; fb[1] = bb.y; fb[2] = bb.z; fb[3] = bb.w;
            *fs = sc; *fl = (float)s_sel_c[tid];
        } else {
            fb[0] = -1.0f; fb[1] = -1.0f; fb[2] = -1.0f; fb[3] = -1.0f;
            *fs = -1.0f; *fl = -1.0f;
        }
    }
}

// ---------------- host launcher ----------------
#define SMEM2_BYTES ((CAP * 2 + MAXV * 5 + MAXV * WMAX) * 4)

extern "C" void kernel_launch(void* const* d_in, const int* in_sizes, int n_in,
                              void* d_out, int out_size) {
    const float* boxes = (const float*)d_in[0];           // [2,20000,4]
    const float* cls   = (const float*)d_in[1];           // [2,20000,80]
    const float* cen   = (const float*)d_in[2];           // [2,20000,1]
    float* out = (float*)d_out;                           // fb(2400) | fs(600) | fl(600)

    cudaFuncSetAttribute(sort_nms_kernel,
                         cudaFuncAttributeMaxDynamicSharedMemorySize, SMEM2_BYTES);

    zero_kernel<<<1, 256>>>();
    const int total4 = B_IMG * N_BOX * C_CLS / 4;
    compact_kernel<<<(total4 + 255) / 256, 256>>>((const float4*)cls, cen);
    sort_nms_kernel<<<BC, 256, SMEM2_BYTES>>>(boxes);
    merge_kernel<<<B_IMG, 512>>>(boxes, out);
}

// round 3
// speedup vs baseline: 1.4965x; 1.1994x over previous
#include <cuda_runtime.h>
#include <float.h>

#define B_IMG 2
#define N_BOX 20000
#define C_CLS 80
#define BC (B_IMG * C_CLS)
#define CAP 1024            // per-(b,c) candidate capacity (mean ~400, sigma ~20)
#define PRE_K 1000
#define MAXV 640            // fast-path NMS limit (12 sigma above mean); fallback beyond
#define WMAX ((MAXV + 31) / 32)   // 20
#define MAX_DET 300
#define SCORE_THR 0.05f
#define IOU_THR 0.5f
#define POOL (C_CLS * MAX_DET)    // 24000 pooled slots per image
#define NB 2048                   // histogram buckets (max)
#define CCAP 2048                 // collected-candidate capacity

// ---------------- scratch (no allocations allowed) ----------------
__device__ int   g_cand_count[BC];
__device__ float g_cand_score[BC * CAP];
__device__ int   g_cand_idx[BC * CAP];
__device__ int   g_keep_count[BC];
__device__ float g_keep_score[BC * MAX_DET];
__device__ int   g_keep_idx[BC * MAX_DET];

// ---------------- K0: zero counters ----------------
__global__ void zero_kernel() {
    int t = threadIdx.x;
    if (t < BC) g_cand_count[t] = 0;
}

// ---------------- K1: threshold + compact (float4 reads) ----------------
__global__ void compact_kernel(const float4* __restrict__ cls4,
                               const float* __restrict__ cen) {
    int q = blockIdx.x * blockDim.x + threadIdx.x;
    const int total4 = B_IMG * N_BOX * C_CLS / 4;
    if (q >= total4) return;
    float4 v = cls4[q];
    float vv[4] = {v.x, v.y, v.z, v.w};
    int base = q * 4;
    #pragma unroll
    for (int k = 0; k < 4; k++) {
        float raw = vv[k];
        if (raw > SCORE_THR) {
            int e = base + k;
            int c = e % C_CLS;
            int n = (e / C_CLS) % N_BOX;
            int b = e / (N_BOX * C_CLS);
            float s = sqrtf(raw * cen[b * N_BOX + n]);
            int bc = b * C_CLS + c;
            int pos = atomicAdd(&g_cand_count[bc], 1);
            if (pos < CAP) {
                g_cand_score[bc * CAP + pos] = s;
                g_cand_idx[bc * CAP + pos]   = n;
            }
        }
    }
}

// ---------------- K2: per-(b,c) sort + bitmask NMS (packed 64-bit keys) ----------------
__global__ __launch_bounds__(256) void sort_nms_kernel(const float* __restrict__ boxes) {
    extern __shared__ unsigned char dynbuf[];
    unsigned long long* s_key = (unsigned long long*)dynbuf;      // CAP
    float*    s_x1 = (float*)(s_key + CAP);                       // MAXV each
    float*    s_y1 = s_x1 + MAXV;
    float*    s_x2 = s_y1 + MAXV;
    float*    s_y2 = s_x2 + MAXV;
    float*    s_ar = s_y2 + MAXV;
    unsigned* s_mask = (unsigned*)(s_ar + MAXV);                  // MAXV * WMAX

    const int bc  = blockIdx.x;
    const int b   = bc / C_CLS;
    const int tid = threadIdx.x;
    const int bd  = blockDim.x;

    int V = g_cand_count[bc];
    if (V > CAP) V = CAP;
    int M = 1;
    while (M < V) M <<= 1;

    for (int i = tid; i < M; i += bd) {
        if (i < V) {
            unsigned sb = __float_as_uint(g_cand_score[bc * CAP + i]);  // positive -> order-preserving
            unsigned ix = (unsigned)g_cand_idx[bc * CAP + i];
            s_key[i] = ((unsigned long long)sb << 32) | (unsigned)(~ix);
        } else {
            s_key[i] = 0ull;
        }
    }
    __syncthreads();

    // bitonic sort descending: score desc, tie -> smaller idx first
    for (int k = 2; k <= M; k <<= 1) {
        for (int j = k >> 1; j > 0; j >>= 1) {
            for (int i = tid; i < M; i += bd) {
                int ixj = i ^ j;
                if (ixj > i) {
                    unsigned long long a = s_key[i], c2 = s_key[ixj];
                    bool up = ((i & k) == 0);
                    if (up ? (a < c2) : (a > c2)) { s_key[i] = c2; s_key[ixj] = a; }
                }
            }
            __syncthreads();
        }
    }

    int K_eff = V < PRE_K ? V : PRE_K;

    if (V <= MAXV) {
        // -------- fast path: bitmask NMS --------
        for (int i = tid; i < K_eff; i += bd) {
            int n = (int)(~((unsigned)s_key[i]));
            float4 bb = reinterpret_cast<const float4*>(boxes)[b * N_BOX + n];
            s_x1[i] = bb.x; s_y1[i] = bb.y; s_x2[i] = bb.z; s_y2[i] = bb.w;
            s_ar[i] = (bb.z - bb.x) * (bb.w - bb.y);
        }
        __syncthreads();

        int W = (K_eff + 31) >> 5;
        for (int t = tid; t < K_eff * W; t += bd) {
            int i = t / W, w = t % W;
            unsigned m = 0;
            int jb = w << 5;
            if (jb + 31 > i) {
                float xi1 = s_x1[i], yi1 = s_y1[i], xi2 = s_x2[i], yi2 = s_y2[i], ai = s_ar[i];
                int jend = min(jb + 32, K_eff);
                for (int j = max(jb, i + 1); j < jend; j++) {
                    float w_ = fmaxf(fminf(xi2, s_x2[j]) - fmaxf(xi1, s_x1[j]), 0.0f);
                    float h_ = fmaxf(fminf(yi2, s_y2[j]) - fmaxf(yi1, s_y1[j]), 0.0f);
                    float inter = w_ * h_;
                    float uni = ai + s_ar[j] - inter;
                    if (inter / fmaxf(uni, 1e-8f) > IOU_THR) m |= 1u << (j - jb);
                }
            }
            s_mask[t] = m;
        }
        __syncthreads();

        if (tid < 32) {
            unsigned sup = 0;   // lane l owns suppressed bits for [32l, 32l+32)
            int nk = 0;
            for (int i = 0; i < K_eff && nk < MAX_DET; i++) {
                unsigned ow = __shfl_sync(0xffffffffu, sup, i >> 5);
                if (!(ow & (1u << (i & 31)))) {
                    if (tid == 0) {
                        unsigned long long kk = s_key[i];
                        g_keep_score[bc * MAX_DET + nk] = __uint_as_float((unsigned)(kk >> 32));
                        g_keep_idx[bc * MAX_DET + nk]   = (int)(~((unsigned)kk));
                    }
                    if (tid < W) sup |= s_mask[i * W + tid];
                    nk++;
                }
            }
            if (tid == 0) g_keep_count[bc] = nk;
        }
    } else {
        // -------- slow fallback (barrier greedy, boxes from global) --------
        unsigned char* sup = (unsigned char*)s_mask;
        __shared__ int s_nk;
        for (int i = tid; i < K_eff; i += bd) sup[i] = 0;
        if (tid == 0) s_nk = 0;
        __syncthreads();
        for (int i = 0; i < K_eff; i++) {
            if (!sup[i]) {
                unsigned long long ki = s_key[i];
                int ni = (int)(~((unsigned)ki));
                if (tid == 0) {
                    int nk = s_nk;
                    g_keep_score[bc * MAX_DET + nk] = __uint_as_float((unsigned)(ki >> 32));
                    g_keep_idx[bc * MAX_DET + nk]   = ni;
                    s_nk = nk + 1;
                }
                float4 bi = reinterpret_cast<const float4*>(boxes)[b * N_BOX + ni];
                float ai = (bi.z - bi.x) * (bi.w - bi.y);
                for (int j = i + 1 + tid; j < K_eff; j += bd) {
                    if (!sup[j]) {
                        int nj = (int)(~((unsigned)s_key[j]));
                        float4 bj = reinterpret_cast<const float4*>(boxes)[b * N_BOX + nj];
                        float aj = (bj.z - bj.x) * (bj.w - bj.y);
                        float w_ = fmaxf(fminf(bi.z, bj.z) - fmaxf(bi.x, bj.x), 0.0f);
                        float h_ = fmaxf(fminf(bi.w, bj.w) - fmaxf(bi.y, bj.y), 0.0f);
                        float inter = w_ * h_;
                        float uni = ai + aj - inter;
                        if (inter / fmaxf(uni, 1e-8f) > IOU_THR) sup[j] = 1;
                    }
                }
                __syncthreads();
                if (s_nk >= MAX_DET) break;
            }
        }
        if (tid == 0) g_keep_count[bc] = (s_nk <= MAX_DET) ? s_nk : MAX_DET;
    }
}

// ---------------- K3: per-image radix-select top-300 + small bitonic ----------------
// Finds the bucket containing element #rem (counting from highest bucket).
// res[0] = bucket (-1 if total < rem), res[1] = count strictly above that bucket.
__device__ __forceinline__ void find_cross(const int* hist, int nb, int rem,
                                           int tid, int* scan, int* res) {
    int chunk = nb / 512;
    int base = tid * chunk;
    int lsum = 0;
    for (int k = 0; k < chunk; k++) lsum += hist[base + k];
    scan[tid] = lsum;
    __syncthreads();
    for (int off = 1; off < 512; off <<= 1) {
        int v = (tid + off < 512) ? scan[tid + off] : 0;
        __syncthreads();
        scan[tid] += v;
        __syncthreads();
    }
    int incl = scan[tid];                 // entries with bucket >= base
    int total = scan[0];
    if (tid == 0 && total < rem) { res[0] = -1; res[1] = total; }
    if (total >= rem) {
        int after = incl - lsum;          // entries with bucket >= base+chunk
        if (after < rem && rem <= incl) { // crossing inside my chunk
            int cum = after;
            for (int k = chunk - 1; k >= 0; k--) {
                int h = hist[base + k];
                cum += h;
                if (cum >= rem) { res[0] = base + k; res[1] = cum - h; break; }
            }
        }
    }
}

__global__ __launch_bounds__(512) void merge_kernel(const float* __restrict__ boxes,
                                                    float* __restrict__ out) {
    extern __shared__ unsigned char dynbuf[];
    unsigned long long* s_key = (unsigned long long*)dynbuf;      // CCAP
    unsigned* s_u  = (unsigned*)(s_key + CCAP);                   // POOL
    int*      hist = (int*)(s_u + POOL);                          // NB
    int*      scan = hist + NB;                                   // 512
    int*      s_m  = scan + 512;                                  // C_CLS
    __shared__ int s_res[2];
    __shared__ int s_ncoll;

    const int b   = blockIdx.x;
    const int tid = threadIdx.x;
    const int bd  = 512;

    if (tid < C_CLS) s_m[tid] = g_keep_count[b * C_CLS + tid];
    for (int i = tid; i < NB; i += bd) hist[i] = 0;
    if (tid == 0) s_ncoll = 0;
    __syncthreads();

    // pass 1: stage scores in SMEM + top-10-bit histogram
    for (int t = tid; t < POOL; t += bd) {
        int c = t / MAX_DET, r = t % MAX_DET;
        unsigned u = 0;
        if (r < s_m[c]) u = __float_as_uint(g_keep_score[(b * C_CLS + c) * MAX_DET + r]);
        s_u[t] = u;
        if (u) atomicAdd(&hist[u >> 22], 1);
    }
    __syncthreads();
    find_cross(hist, 1024, MAX_DET, tid, scan, s_res);
    __syncthreads();
    int b1 = s_res[0], na1 = s_res[1];
    unsigned Tu = 0;
    bool found = (b1 >= 0);

    if (found) {
        // pass 2: middle 11 bits within boundary bucket
        for (int i = tid; i < NB; i += bd) hist[i] = 0;
        __syncthreads();
        for (int t = tid; t < POOL; t += bd) {
            unsigned u = s_u[t];
            if (u && (int)(u >> 22) == b1) atomicAdd(&hist[(u >> 11) & 0x7FF], 1);
        }
        __syncthreads();
        find_cross(hist, 2048, MAX_DET - na1, tid, scan, s_res);
        __syncthreads();
        int b2 = s_res[0], na2 = s_res[1];
        unsigned p2 = ((unsigned)b1 << 11) | (unsigned)b2;

        // pass 3: low 11 bits within (b1,b2) sub-bucket -> exact threshold
        for (int i = tid; i < NB; i += bd) hist[i] = 0;
        __syncthreads();
        for (int t = tid; t < POOL; t += bd) {
            unsigned u = s_u[t];
            if (u && (u >> 11) == p2) atomicAdd(&hist[u & 0x7FF], 1);
        }
        __syncthreads();
        find_cross(hist, 2048, MAX_DET - na1 - na2, tid, scan, s_res);
        __syncthreads();
        Tu = (p2 << 11) | (unsigned)s_res[0];
    }
    __syncthreads();

    // collect all entries >= exact threshold (ties included; sort resolves order)
    for (int t = tid; t < POOL; t += bd) {
        unsigned u = s_u[t];
        if (u && (!found || u >= Tu)) {
            int pos = atomicAdd(&s_ncoll, 1);
            if (pos < CCAP)
                s_key[pos] = ((unsigned long long)u << 16) | (unsigned)(0xFFFF - t);
        }
    }
    __syncthreads();
    int Ncoll = s_ncoll < CCAP ? s_ncoll : CCAP;
    int M2 = 1;
    while (M2 < Ncoll) M2 <<= 1;
    for (int i = tid; i < M2; i += bd) if (i >= Ncoll) s_key[i] = 0ull;
    __syncthreads();

    // bitonic sort descending (score desc, flat index asc)
    for (int k = 2; k <= M2; k <<= 1) {
        for (int j = k >> 1; j > 0; j >>= 1) {
            for (int i = tid; i < M2; i += bd) {
                int ixj = i ^ j;
                if (ixj > i) {
                    unsigned long long a = s_key[i], c2 = s_key[ixj];
                    bool up = ((i & k) == 0);
                    if (up ? (a < c2) : (a > c2)) { s_key[i] = c2; s_key[ixj] = a; }
                }
            }
            __syncthreads();
        }
    }

    if (tid < MAX_DET) {
        float* fb = out + b * (MAX_DET * 4) + tid * 4;
        float* fs = out + B_IMG * MAX_DET * 4 + b * MAX_DET + tid;
        float* fl = out + B_IMG * MAX_DET * 4 + B_IMG * MAX_DET + b * MAX_DET + tid;
        if (tid < Ncoll) {
            unsigned long long kk = s_key[tid];
            unsigned u = (unsigned)(kk >> 32) << 16 | ((unsigned)(kk >> 16) & 0xFFFF);
            // decode: key = (u << 16) | (0xFFFF - flat)
            u = (unsigned)(kk >> 16);
            int flat = 0xFFFF - (int)(kk & 0xFFFF);
            int c = flat / MAX_DET, r = flat % MAX_DET;
            int n = g_keep_idx[(b * C_CLS + c) * MAX_DET + r];
            float4 bb = reinterpret_cast<const float4*>(boxes)[b * N_BOX + n];
            fb[0] = bb.x; fb[1] = bb.y; fb[2] = bb.z; fb[3] = bb.w;
            *fs = __uint_as_float(u);
            *fl = (float)c;
        } else {
            fb[0] = -1.0f; fb[1] = -1.0f; fb[2] = -1.0f; fb[3] = -1.0f;
            *fs = -1.0f; *fl = -1.0f;
        }
    }
}

// ---------------- host launcher ----------------
#define SMEM2_BYTES (CAP * 8 + MAXV * 5 * 4 + MAXV * WMAX * 4)
#define SMEM3_BYTES (CCAP * 8 + POOL * 4 + NB * 4 + 512 * 4 + C_CLS * 4)

extern "C" void kernel_launch(void* const* d_in, const int* in_sizes, int n_in,
                              void* d_out, int out_size) {
    const float* boxes = (const float*)d_in[0];           // [2,20000,4]
    const float* cls   = (const float*)d_in[1];           // [2,20000,80]
    const float* cen   = (const float*)d_in[2];           // [2,20000,1]
    float* out = (float*)d_out;                           // fb(2400) | fs(600) | fl(600)

    cudaFuncSetAttribute(sort_nms_kernel,
                         cudaFuncAttributeMaxDynamicSharedMemorySize, SMEM2_BYTES);
    cudaFuncSetAttribute(merge_kernel,
                         cudaFuncAttributeMaxDynamicSharedMemorySize, SMEM3_BYTES);

    zero_kernel<<<1, 256>>>();
    const int total4 = B_IMG * N_BOX * C_CLS / 4;
    compact_kernel<<<(total4 + 255) / 256, 256>>>((const float4*)cls, cen);
    sort_nms_kernel<<<BC, 256, SMEM2_BYTES>>>(boxes);
    merge_kernel<<<B_IMG, 512, SMEM3_BYTES>>>(boxes, out);
}

// round 4
// speedup vs baseline: 1.7617x; 1.1772x over previous
#include <cuda_runtime.h>
#include <float.h>

#define B_IMG 2
#define N_BOX 20000
#define C_CLS 80
#define BC (B_IMG * C_CLS)
#define CAP 1024            // per-(b,c) candidate capacity (mean ~380, sigma ~20)
#define CPAD 32             // counter padding: 128B stride -> independent L2 slices
#define PRE_K 1000
#define MAXV 512            // fast-path NMS limit (~7 sigma above mean); fallback beyond
#define WMAX (MAXV / 32)    // 16
#define MAX_DET 300
#define SCORE_THR 0.05f
#define IOU_THR 0.5f
#define POOL (C_CLS * MAX_DET)    // 24000 (fallback pool)
#define WIN 64                    // truncated merge window per class
#define NB 2048
#define CCAP 2048

// ---------------- scratch (no allocations allowed) ----------------
__device__ int   g_cand_count[BC * CPAD];
__device__ float g_cand_score[BC * CAP];
__device__ int   g_cand_idx[BC * CAP];
__device__ int   g_keep_count[BC];
__device__ float g_keep_score[BC * MAX_DET];
__device__ int   g_keep_idx[BC * MAX_DET];

// ---------------- K0: zero padded counters ----------------
__global__ void zero_kernel() {
    for (int t = threadIdx.x; t < BC * CPAD; t += blockDim.x) g_cand_count[t] = 0;
}

// ---------------- K1: threshold + compact (float4 reads, padded atomics) ----------------
__global__ void compact_kernel(const float4* __restrict__ cls4,
                               const float* __restrict__ cen) {
    int q = blockIdx.x * blockDim.x + threadIdx.x;
    const int total4 = B_IMG * N_BOX * C_CLS / 4;
    if (q >= total4) return;
    float4 v = cls4[q];
    float vv[4] = {v.x, v.y, v.z, v.w};
    int base = q * 4;
    #pragma unroll
    for (int k = 0; k < 4; k++) {
        float raw = vv[k];
        if (raw > SCORE_THR) {
            int e = base + k;
            int c = e % C_CLS;
            int n = (e / C_CLS) % N_BOX;
            int b = e / (N_BOX * C_CLS);
            float s = sqrtf(raw * cen[b * N_BOX + n]);
            int bc = b * C_CLS + c;
            int pos = atomicAdd(&g_cand_count[bc * CPAD], 1);
            if (pos < CAP) {
                g_cand_score[bc * CAP + pos] = s;
                g_cand_idx[bc * CAP + pos]   = n;
            }
        }
    }
}

// ---------------- K2: per-(b,c) sort + bitmask NMS ----------------
__global__ __launch_bounds__(256) void sort_nms_kernel(const float* __restrict__ boxes) {
    extern __shared__ unsigned char dynbuf[];
    float4*   s_box = (float4*)dynbuf;                            // MAXV
    unsigned long long* s_key = (unsigned long long*)(s_box + MAXV); // CAP
    unsigned* s_mask = (unsigned*)(s_key + CAP);                  // MAXV * WMAX
    int*      s_any  = (int*)(s_mask + MAXV * WMAX);              // MAXV

    const int bc  = blockIdx.x;
    const int b   = bc / C_CLS;
    const int tid = threadIdx.x;
    const int bd  = blockDim.x;

    int V = g_cand_count[bc * CPAD];
    if (V > CAP) V = CAP;
    int M = 1;
    while (M < V) M <<= 1;

    for (int i = tid; i < M; i += bd) {
        if (i < V) {
            unsigned sb = __float_as_uint(g_cand_score[bc * CAP + i]);
            unsigned ix = (unsigned)g_cand_idx[bc * CAP + i];
            s_key[i] = ((unsigned long long)sb << 32) | (unsigned)(~ix);
        } else {
            s_key[i] = 0ull;
        }
    }
    __syncthreads();

    // bitonic sort descending: score desc, tie -> smaller idx first
    for (int k = 2; k <= M; k <<= 1) {
        for (int j = k >> 1; j > 0; j >>= 1) {
            for (int i = tid; i < M; i += bd) {
                int ixj = i ^ j;
                if (ixj > i) {
                    unsigned long long a = s_key[i], c2 = s_key[ixj];
                    bool up = ((i & k) == 0);
                    if (up ? (a < c2) : (a > c2)) { s_key[i] = c2; s_key[ixj] = a; }
                }
            }
            __syncthreads();
        }
    }

    int K_eff = V < PRE_K ? V : PRE_K;

    if (V <= MAXV) {
        // -------- fast path: bitmask NMS --------
        for (int i = tid; i < K_eff; i += bd) {
            int n = (int)(~((unsigned)s_key[i]));
            s_box[i] = reinterpret_cast<const float4*>(boxes)[b * N_BOX + n];
            s_any[i] = 0;
        }
        __syncthreads();

        int W = (K_eff + 31) >> 5;
        for (int t = tid; t < K_eff * W; t += bd) {
            int i = t / W, w = t % W;
            unsigned m = 0;
            int jb = w << 5;
            if (jb + 31 > i) {
                float4 bi = s_box[i];
                float ai = (bi.z - bi.x) * (bi.w - bi.y);
                int jend = min(jb + 32, K_eff);
                for (int j = max(jb, i + 1); j < jend; j++) {
                    float4 bj = s_box[j];
                    float w_ = fmaxf(fminf(bi.z, bj.z) - fmaxf(bi.x, bj.x), 0.0f);
                    float h_ = fmaxf(fminf(bi.w, bj.w) - fmaxf(bi.y, bj.y), 0.0f);
                    float inter = w_ * h_;
                    float uni = ai + (bj.z - bj.x) * (bj.w - bj.y) - inter;
                    if (inter / fmaxf(uni, 1e-8f) > IOU_THR) m |= 1u << (j - jb);
                }
                if (m) s_any[i] = 1;   // benign race: same value
            }
            s_mask[t] = m;
        }
        __syncthreads();

        if (tid < 32) {
            unsigned sup = 0;   // lane l owns suppressed bits for [32l, 32l+32)
            int nk = 0;
            for (int i = 0; i < K_eff && nk < MAX_DET; i++) {
                unsigned ow = __shfl_sync(0xffffffffu, sup, i >> 5);
                if (!(ow & (1u << (i & 31)))) {
                    if (tid == 0) {
                        unsigned long long kk = s_key[i];
                        g_keep_score[bc * MAX_DET + nk] = __uint_as_float((unsigned)(kk >> 32));
                        g_keep_idx[bc * MAX_DET + nk]   = (int)(~((unsigned)kk));
                    }
                    if (s_any[i] && tid < W) sup |= s_mask[i * W + tid];
                    nk++;
                }
            }
            if (tid == 0) g_keep_count[bc] = nk;
        }
    } else {
        // -------- slow fallback (barrier greedy, boxes from global) --------
        unsigned char* sup = (unsigned char*)s_mask;
        __shared__ int s_nk;
        for (int i = tid; i < K_eff; i += bd) sup[i] = 0;
        if (tid == 0) s_nk = 0;
        __syncthreads();
        for (int i = 0; i < K_eff; i++) {
            if (!sup[i]) {
                unsigned long long ki = s_key[i];
                int ni = (int)(~((unsigned)ki));
                if (tid == 0) {
                    int nk = s_nk;
                    g_keep_score[bc * MAX_DET + nk] = __uint_as_float((unsigned)(ki >> 32));
                    g_keep_idx[bc * MAX_DET + nk]   = ni;
                    s_nk = nk + 1;
                }
                float4 bi = reinterpret_cast<const float4*>(boxes)[b * N_BOX + ni];
                float ai = (bi.z - bi.x) * (bi.w - bi.y);
                for (int j = i + 1 + tid; j < K_eff; j += bd) {
                    if (!sup[j]) {
                        int nj = (int)(~((unsigned)s_key[j]));
                        float4 bj = reinterpret_cast<const float4*>(boxes)[b * N_BOX + nj];
                        float aj = (bj.z - bj.x) * (bj.w - bj.y);
                        float w_ = fmaxf(fminf(bi.z, bj.z) - fmaxf(bi.x, bj.x), 0.0f);
                        float h_ = fmaxf(fminf(bi.w, bj.w) - fmaxf(bi.y, bj.y), 0.0f);
                        float inter = w_ * h_;
                        float uni = ai + aj - inter;
                        if (inter / fmaxf(uni, 1e-8f) > IOU_THR) sup[j] = 1;
                    }
                }
                __syncthreads();
                if (s_nk >= MAX_DET) break;
            }
        }
        if (tid == 0) g_keep_count[bc] = (s_nk <= MAX_DET) ? s_nk : MAX_DET;
    }
}

// ---------------- K3: per-image radix-select top-300 (truncated pool + exact fallback) ----------------
__device__ __forceinline__ void find_cross(const int* hist, int nb, int rem,
                                           int tid, int* scan, int* res) {
    int chunk = nb / 512;
    int base = tid * chunk;
    int lsum = 0;
    for (int k = 0; k < chunk; k++) lsum += hist[base + k];
    scan[tid] = lsum;
    __syncthreads();
    for (int off = 1; off < 512; off <<= 1) {
        int v = (tid + off < 512) ? scan[tid + off] : 0;
        __syncthreads();
        scan[tid] += v;
        __syncthreads();
    }
    int incl = scan[tid];                 // entries with bucket >= base
    int total = scan[0];
    if (tid == 0 && total < rem) { res[0] = -1; res[1] = total; }
    if (total >= rem) {
        int after = incl - lsum;          // entries with bucket >= base+chunk
        if (after < rem && rem <= incl) {
            int cum = after;
            for (int k = chunk - 1; k >= 0; k--) {
                int h = hist[base + k];
                cum += h;
                if (cum >= rem) { res[0] = base + k; res[1] = cum - h; break; }
            }
        }
    }
}

__global__ __launch_bounds__(512) void merge_kernel(const float* __restrict__ boxes,
                                                    float* __restrict__ out) {
    extern __shared__ unsigned char dynbuf[];
    unsigned long long* s_key = (unsigned long long*)dynbuf;      // CCAP
    unsigned* s_u  = (unsigned*)(s_key + CCAP);                   // POOL
    int*      hist = (int*)(s_u + POOL);                          // NB
    int*      scan = hist + NB;                                   // 512
    int*      s_cnt = scan + 512;                                 // C_CLS
    __shared__ int s_res[2];
    __shared__ int s_ncoll;
    __shared__ unsigned s_maxtr;

    const int b   = blockIdx.x;
    const int tid = threadIdx.x;
    const int bd  = 512;

    if (tid < C_CLS) s_cnt[tid] = g_keep_count[b * C_CLS + tid];
    if (tid == 0) { s_maxtr = 0; s_ncoll = 0; }
    __syncthreads();
    // largest truncated-away score (lists are sorted: element WIN is the max beyond the window)
    if (tid < C_CLS && s_cnt[tid] > WIN)
        atomicMax(&s_maxtr, __float_as_uint(g_keep_score[(b * C_CLS + tid) * MAX_DET + WIN]));
    __syncthreads();

    int win = WIN, pool;
    unsigned Tu = 0;
    bool found = false;

    for (int mode = 0; mode < 2; mode++) {
        win = mode ? MAX_DET : WIN;
        pool = C_CLS * win;

        for (int i = tid; i < 1024; i += bd) hist[i] = 0;
        __syncthreads();
        for (int t = tid; t < pool; t += bd) {
            int c = t / win, r = t % win;
            unsigned u = (r < s_cnt[c])
                       ? __float_as_uint(g_keep_score[(b * C_CLS + c) * MAX_DET + r]) : 0;
            s_u[t] = u;
            if (u) atomicAdd(&hist[u >> 22], 1);
        }
        __syncthreads();
        find_cross(hist, 1024, MAX_DET, tid, scan, s_res);
        __syncthreads();
        int b1 = s_res[0], na1 = s_res[1];
        found = (b1 >= 0);
        Tu = 0;

        if (found) {
            for (int i = tid; i < NB; i += bd) hist[i] = 0;
            __syncthreads();
            for (int t = tid; t < pool; t += bd) {
                unsigned u = s_u[t];
                if (u && (int)(u >> 22) == b1) atomicAdd(&hist[(u >> 11) & 0x7FF], 1);
            }
            __syncthreads();
            find_cross(hist, 2048, MAX_DET - na1, tid, scan, s_res);
            __syncthreads();
            int b2 = s_res[0], na2 = s_res[1];
            unsigned p2 = ((unsigned)b1 << 11) | (unsigned)b2;

            for (int i = tid; i < NB; i += bd) hist[i] = 0;
            __syncthreads();
            for (int t = tid; t < pool; t += bd) {
                unsigned u = s_u[t];
                if (u && (u >> 11) == p2) atomicAdd(&hist[u & 0x7FF], 1);
            }
            __syncthreads();
            find_cross(hist, 2048, MAX_DET - na1 - na2, tid, scan, s_res);
            __syncthreads();
            Tu = (p2 << 11) | (unsigned)s_res[0];
        }
        __syncthreads();

        if (mode == 0) {
            // exact validity: selected threshold strictly above every truncated score
            bool valid = found ? (Tu > s_maxtr) : (s_maxtr == 0);
            if (valid) break;
        }
    }

    // collect all entries >= exact threshold
    for (int t = tid; t < pool; t += bd) {
        unsigned u = s_u[t];
        if (u && (!found || u >= Tu)) {
            int pos = atomicAdd(&s_ncoll, 1);
            if (pos < CCAP) {
                int c = t / win, r = t % win;
                int flat = c * MAX_DET + r;        // global tie-break order
                s_key[pos] = ((unsigned long long)u << 16) | (unsigned)(0xFFFF - flat);
            }
        }
    }
    __syncthreads();
    int Ncoll = s_ncoll < CCAP ? s_ncoll : CCAP;
    int M2 = 1;
    while (M2 < Ncoll) M2 <<= 1;
    for (int i = tid; i < M2; i += bd) if (i >= Ncoll) s_key[i] = 0ull;
    __syncthreads();

    for (int k = 2; k <= M2; k <<= 1) {
        for (int j = k >> 1; j > 0; j >>= 1) {
            for (int i = tid; i < M2; i += bd) {
                int ixj = i ^ j;
                if (ixj > i) {
                    unsigned long long a = s_key[i], c2 = s_key[ixj];
                    bool up = ((i & k) == 0);
                    if (up ? (a < c2) : (a > c2)) { s_key[i] = c2; s_key[ixj] = a; }
                }
            }
            __syncthreads();
        }
    }

    if (tid < MAX_DET) {
        float* fb = out + b * (MAX_DET * 4) + tid * 4;
        float* fs = out + B_IMG * MAX_DET * 4 + b * MAX_DET + tid;
        float* fl = out + B_IMG * MAX_DET * 4 + B_IMG * MAX_DET + b * MAX_DET + tid;
        if (tid < Ncoll) {
            unsigned long long kk = s_key[tid];
            unsigned u = (unsigned)(kk >> 16);
            int flat = 0xFFFF - (int)(kk & 0xFFFF);
            int c = flat / MAX_DET, r = flat % MAX_DET;
            int n = g_keep_idx[(b * C_CLS + c) * MAX_DET + r];
            float4 bb = reinterpret_cast<const float4*>(boxes)[b * N_BOX + n];
            fb[0] = bb.x; fb[1] = bb.y; fb[2] = bb.z; fb[3] = bb.w;
            *fs = __uint_as_float(u);
            *fl = (float)c;
        } else {
            fb[0] = -1.0f; fb[1] = -1.0f; fb[2] = -1.0f; fb[3] = -1.0f;
            *fs = -1.0f; *fl = -1.0f;
        }
    }
}

// ---------------- host launcher ----------------
#define SMEM2_BYTES (MAXV * 16 + CAP * 8 + MAXV * WMAX * 4 + MAXV * 4)
#define SMEM3_BYTES (CCAP * 8 + POOL * 4 + NB * 4 + 512 * 4 + C_CLS * 4)

extern "C" void kernel_launch(void* const* d_in, const int* in_sizes, int n_in,
                              void* d_out, int out_size) {
    const float* boxes = (const float*)d_in[0];           // [2,20000,4]
    const float* cls   = (const float*)d_in[1];           // [2,20000,80]
    const float* cen   = (const float*)d_in[2];           // [2,20000,1]
    float* out = (float*)d_out;                           // fb(2400) | fs(600) | fl(600)

    cudaFuncSetAttribute(sort_nms_kernel,
                         cudaFuncAttributeMaxDynamicSharedMemorySize, SMEM2_BYTES);
    cudaFuncSetAttribute(merge_kernel,
                         cudaFuncAttributeMaxDynamicSharedMemorySize, SMEM3_BYTES);

    zero_kernel<<<1, 512>>>();
    const int total4 = B_IMG * N_BOX * C_CLS / 4;
    compact_kernel<<<(total4 + 255) / 256, 256>>>((const float4*)cls, cen);
    sort_nms_kernel<<<BC, 256, SMEM2_BYTES>>>(boxes);
    merge_kernel<<<B_IMG, 512, SMEM3_BYTES>>>(boxes, out);
}

// round 5
// speedup vs baseline: 2.1525x; 1.2219x over previous
#include <cuda_runtime.h>
#include <float.h>

#define B_IMG 2
#define N_BOX 20000
#define C_CLS 80
#define BC (B_IMG * C_CLS)          // 160
#define CAP 1024
#define CPAD 32
#define PRE_K 1000
#define MAXV 512
#define WMAX (MAXV / 32)            // 16
#define MAX_DET 300
#define SCORE_THR 0.05f
#define IOU_THR 0.5f
#define WIN 64
#define NB 2048
#define CCAP 2048
#define GRID 160
#define TPB 512
#define SMEM_BYTES 51200            // max(phase2=51200, phase3=47424)

// ---------------- scratch (no allocations allowed) ----------------
__device__ int   g_b1, g_b2;        // grid barrier counters (start 0, self-resetting)
__device__ int   g_cand_count[BC * CPAD];
__device__ float g_cand_score[BC * CAP];
__device__ int   g_cand_idx[BC * CAP];
__device__ int   g_keep_count[BC];
__device__ float g_keep_score[BC * MAX_DET];
__device__ int   g_keep_idx[BC * MAX_DET];

// block-parallel suffix-scan bucket finder (512 threads)
__device__ __forceinline__ void find_cross(const int* hist, int nb, int rem,
                                           int tid, int* scan, int* res) {
    int chunk = nb / TPB;
    int base = tid * chunk;
    int lsum = 0;
    for (int k = 0; k < chunk; k++) lsum += hist[base + k];
    scan[tid] = lsum;
    __syncthreads();
    for (int off = 1; off < TPB; off <<= 1) {
        int v = (tid + off < TPB) ? scan[tid + off] : 0;
        __syncthreads();
        scan[tid] += v;
        __syncthreads();
    }
    int incl = scan[tid];
    int total = scan[0];
    if (tid == 0 && total < rem) { res[0] = -1; res[1] = total; }
    if (total >= rem) {
        int after = incl - lsum;
        if (after < rem && rem <= incl) {
            int cum = after;
            for (int k = chunk - 1; k >= 0; k--) {
                int h = hist[base + k];
                cum += h;
                if (cum >= rem) { res[0] = base + k; res[1] = cum - h; break; }
            }
        }
    }
}

__global__ __launch_bounds__(TPB, 2)
void fused_kernel(const float* __restrict__ boxes,
                  const float4* __restrict__ cls4,
                  const float* __restrict__ cen,
                  float* __restrict__ out) {
    extern __shared__ unsigned char dynbuf[];
    const int tid = threadIdx.x;
    const int bc  = blockIdx.x;

    // ================= phase 1: threshold + compact =================
    {
        const int total4 = B_IMG * N_BOX * C_CLS / 4;
        for (int q = bc * TPB + tid; q < total4; q += GRID * TPB) {
            float4 v = cls4[q];
            float vv[4] = {v.x, v.y, v.z, v.w};
            int base = q * 4;
            #pragma unroll
            for (int k = 0; k < 4; k++) {
                float raw = vv[k];
                if (raw > SCORE_THR) {
                    int e = base + k;
                    int c = e % C_CLS;
                    int n = (e / C_CLS) % N_BOX;
                    int b = e / (N_BOX * C_CLS);
                    float s = sqrtf(raw * cen[b * N_BOX + n]);
                    int idx = b * C_CLS + c;
                    int pos = atomicAdd(&g_cand_count[idx * CPAD], 1);
                    if (pos < CAP) {
                        g_cand_score[idx * CAP + pos] = s;
                        g_cand_idx[idx * CAP + pos]   = n;
                    }
                }
            }
        }
    }

    // ---- grid barrier 1 ----
    __threadfence();
    __syncthreads();
    if (tid == 0) {
        atomicAdd(&g_b1, 1);
        while (*(volatile int*)&g_b1 < GRID) {}
    }
    __syncthreads();
    __threadfence();

    // ================= phase 2: per-(b,c) sort + bitmask NMS =================
    {
        float4*   s_box = (float4*)dynbuf;                               // MAXV
        unsigned long long* s_key = (unsigned long long*)(s_box + MAXV); // CAP
        unsigned* s_mask = (unsigned*)(s_key + CAP);                     // MAXV*WMAX
        int*      s_any  = (int*)(s_mask + MAXV * WMAX);                 // MAXV

        const int b = bc / C_CLS;
        int V = g_cand_count[bc * CPAD];
        if (V > CAP) V = CAP;
        int M = 1;
        while (M < V) M <<= 1;

        for (int i = tid; i < M; i += TPB) {
            if (i < V) {
                unsigned sb = __float_as_uint(g_cand_score[bc * CAP + i]);
                unsigned ix = (unsigned)g_cand_idx[bc * CAP + i];
                s_key[i] = ((unsigned long long)sb << 32) | (unsigned)(~ix);
            } else {
                s_key[i] = 0ull;
            }
        }
        __syncthreads();
        if (tid == 0) g_cand_count[bc * CPAD] = 0;   // re-zero for next replay

        for (int k = 2; k <= M; k <<= 1) {
            for (int j = k >> 1; j > 0; j >>= 1) {
                for (int i = tid; i < M; i += TPB) {
                    int ixj = i ^ j;
                    if (ixj > i) {
                        unsigned long long a = s_key[i], c2 = s_key[ixj];
                        bool up = ((i & k) == 0);
                        if (up ? (a < c2) : (a > c2)) { s_key[i] = c2; s_key[ixj] = a; }
                    }
                }
                __syncthreads();
            }
        }

        int K_eff = V < PRE_K ? V : PRE_K;

        if (V <= MAXV) {
            for (int i = tid; i < K_eff; i += TPB) {
                int n = (int)(~((unsigned)s_key[i]));
                s_box[i] = reinterpret_cast<const float4*>(boxes)[b * N_BOX + n];
                s_any[i] = 0;
            }
            __syncthreads();

            int W = (K_eff + 31) >> 5;
            for (int t = tid; t < K_eff * W; t += TPB) {
                int i = t / W, w = t % W;
                unsigned m = 0;
                int jb = w << 5;
                if (jb + 31 > i) {
                    float4 bi = s_box[i];
                    float ai = (bi.z - bi.x) * (bi.w - bi.y);
                    int jend = min(jb + 32, K_eff);
                    for (int j = max(jb, i + 1); j < jend; j++) {
                        float4 bj = s_box[j];
                        float w_ = fmaxf(fminf(bi.z, bj.z) - fmaxf(bi.x, bj.x), 0.0f);
                        float h_ = fmaxf(fminf(bi.w, bj.w) - fmaxf(bi.y, bj.y), 0.0f);
                        float inter = w_ * h_;
                        float uni = ai + (bj.z - bj.x) * (bj.w - bj.y) - inter;
                        if (inter / fmaxf(uni, 1e-8f) > IOU_THR) m |= 1u << (j - jb);
                    }
                    if (m) s_any[i] = 1;
                }
                s_mask[t] = m;
            }
            __syncthreads();

            if (tid < 32) {
                unsigned sup = 0;
                int nk = 0;
                for (int i = 0; i < K_eff && nk < MAX_DET; i++) {
                    unsigned ow = __shfl_sync(0xffffffffu, sup, i >> 5);
                    if (!(ow & (1u << (i & 31)))) {
                        if (tid == 0) {
                            unsigned long long kk = s_key[i];
                            g_keep_score[bc * MAX_DET + nk] = __uint_as_float((unsigned)(kk >> 32));
                            g_keep_idx[bc * MAX_DET + nk]   = (int)(~((unsigned)kk));
                        }
                        if (s_any[i] && tid < W) sup |= s_mask[i * W + tid];
                        nk++;
                    }
                }
                if (tid == 0) g_keep_count[bc] = nk;
            }
        } else {
            // slow fallback: barrier greedy, boxes from global
            unsigned char* sup = (unsigned char*)s_mask;
            __shared__ int s_nk;
            for (int i = tid; i < K_eff; i += TPB) sup[i] = 0;
            if (tid == 0) s_nk = 0;
            __syncthreads();
            for (int i = 0; i < K_eff; i++) {
                if (!sup[i]) {
                    unsigned long long ki = s_key[i];
                    int ni = (int)(~((unsigned)ki));
                    if (tid == 0) {
                        int nk = s_nk;
                        g_keep_score[bc * MAX_DET + nk] = __uint_as_float((unsigned)(ki >> 32));
                        g_keep_idx[bc * MAX_DET + nk]   = ni;
                        s_nk = nk + 1;
                    }
                    float4 bi = reinterpret_cast<const float4*>(boxes)[b * N_BOX + ni];
                    float ai = (bi.z - bi.x) * (bi.w - bi.y);
                    for (int j = i + 1 + tid; j < K_eff; j += TPB) {
                        if (!sup[j]) {
                            int nj = (int)(~((unsigned)s_key[j]));
                            float4 bj = reinterpret_cast<const float4*>(boxes)[b * N_BOX + nj];
                            float aj = (bj.z - bj.x) * (bj.w - bj.y);
                            float w_ = fmaxf(fminf(bi.z, bj.z) - fmaxf(bi.x, bj.x), 0.0f);
                            float h_ = fmaxf(fminf(bi.w, bj.w) - fmaxf(bi.y, bj.y), 0.0f);
                            float inter = w_ * h_;
                            float uni = ai + aj - inter;
                            if (inter / fmaxf(uni, 1e-8f) > IOU_THR) sup[j] = 1;
                        }
                    }
                    __syncthreads();
                    if (s_nk >= MAX_DET) break;
                }
            }
            if (tid == 0) g_keep_count[bc] = (s_nk <= MAX_DET) ? s_nk : MAX_DET;
        }
    }

    // ---- grid barrier 2 (last arriver resets g_b1) ----
    __threadfence();
    __syncthreads();
    if (tid == 0) {
        int t = atomicAdd(&g_b2, 1);
        if (t == GRID - 1) g_b1 = 0;             // all blocks passed barrier 1
        while (*(volatile int*)&g_b2 < GRID) {}
    }
    __syncthreads();
    __threadfence();

    if (bc >= B_IMG) return;

    // ================= phase 3: per-image radix-select top-300 =================
    {
        unsigned* s_u   = (unsigned*)dynbuf;                        // C_CLS*WIN
        int*      hist  = (int*)(s_u + C_CLS * WIN);                // NB
        int*      scan  = hist + NB;                                // TPB
        int*      s_cnt = scan + TPB;                               // C_CLS
        unsigned long long* s_key = (unsigned long long*)(s_cnt + C_CLS); // CCAP
        __shared__ int s_res[2];
        __shared__ int s_ncoll;
        __shared__ unsigned s_maxtr;

        const int b = bc;
        if (tid < C_CLS) s_cnt[tid] = g_keep_count[b * C_CLS + tid];
        if (tid == 0) { s_maxtr = 0; s_ncoll = 0; }
        __syncthreads();
        if (tid < C_CLS && s_cnt[tid] > WIN)
            atomicMax(&s_maxtr, __float_as_uint(g_keep_score[(b * C_CLS + tid) * MAX_DET + WIN]));
        __syncthreads();

        unsigned Tu = 0;
        bool found = false;
        int win = WIN, pool = C_CLS * WIN, fmode = 0;

        for (int mode = 0; mode < 2; mode++) {
            win = mode ? MAX_DET : WIN;
            pool = C_CLS * win;
            fmode = mode;

            for (int i = tid; i < 1024; i += TPB) hist[i] = 0;
            __syncthreads();
            for (int t = tid; t < pool; t += TPB) {
                int c = t / win, r = t % win;
                unsigned u = (r < s_cnt[c])
                           ? __float_as_uint(g_keep_score[(b * C_CLS + c) * MAX_DET + r]) : 0;
                if (!mode) s_u[t] = u;
                if (u) atomicAdd(&hist[u >> 22], 1);
            }
            __syncthreads();
            find_cross(hist, 1024, MAX_DET, tid, scan, s_res);
            __syncthreads();
            int b1 = s_res[0], na1 = s_res[1];
            found = (b1 >= 0);
            Tu = 0;

            if (found) {
                for (int i = tid; i < NB; i += TPB) hist[i] = 0;
                __syncthreads();
                for (int t = tid; t < pool; t += TPB) {
                    unsigned u;
                    if (!mode) u = s_u[t];
                    else {
                        int c = t / win, r = t % win;
                        u = (r < s_cnt[c])
                          ? __float_as_uint(g_keep_score[(b * C_CLS + c) * MAX_DET + r]) : 0;
                    }
                    if (u && (int)(u >> 22) == b1) atomicAdd(&hist[(u >> 11) & 0x7FF], 1);
                }
                __syncthreads();
                find_cross(hist, 2048, MAX_DET - na1, tid, scan, s_res);
                __syncthreads();
                int b2 = s_res[0], na2 = s_res[1];
                unsigned p2 = ((unsigned)b1 << 11) | (unsigned)b2;

                for (int i = tid; i < NB; i += TPB) hist[i] = 0;
                __syncthreads();
                for (int t = tid; t < pool; t += TPB) {
                    unsigned u;
                    if (!mode) u = s_u[t];
                    else {
                        int c = t / win, r = t % win;
                        u = (r < s_cnt[c])
                          ? __float_as_uint(g_keep_score[(b * C_CLS + c) * MAX_DET + r]) : 0;
                    }
                    if (u && (u >> 11) == p2) atomicAdd(&hist[u & 0x7FF], 1);
                }
                __syncthreads();
                find_cross(hist, 2048, MAX_DET - na1 - na2, tid, scan, s_res);
                __syncthreads();
                Tu = (p2 << 11) | (unsigned)s_res[0];
            }
            __syncthreads();

            if (mode == 0) {
                bool valid = found ? (Tu > s_maxtr) : (s_maxtr == 0);
                if (valid) break;
            }
        }

        // collect entries >= exact threshold
        for (int t = tid; t < pool; t += TPB) {
            unsigned u;
            int c = t / win, r = t % win;
            if (!fmode) u = s_u[t];
            else u = (r < s_cnt[c])
                   ? __float_as_uint(g_keep_score[(b * C_CLS + c) * MAX_DET + r]) : 0;
            if (u && (!found || u >= Tu)) {
                int pos = atomicAdd(&s_ncoll, 1);
                if (pos < CCAP) {
                    int flat = c * MAX_DET + r;
                    s_key[pos] = ((unsigned long long)u << 16) | (unsigned)(0xFFFF - flat);
                }
            }
        }
        __syncthreads();
        int Ncoll = s_ncoll < CCAP ? s_ncoll : CCAP;
        int M2 = 1;
        while (M2 < Ncoll) M2 <<= 1;
        for (int i = tid; i < M2; i += TPB) if (i >= Ncoll) s_key[i] = 0ull;
        __syncthreads();

        for (int k = 2; k <= M2; k <<= 1) {
            for (int j = k >> 1; j > 0; j >>= 1) {
                for (int i = tid; i < M2; i += TPB) {
                    int ixj = i ^ j;
                    if (ixj > i) {
                        unsigned long long a = s_key[i], c2 = s_key[ixj];
                        bool up = ((i & k) == 0);
                        if (up ? (a < c2) : (a > c2)) { s_key[i] = c2; s_key[ixj] = a; }
                    }
                }
                __syncthreads();
            }
        }

        if (tid < MAX_DET) {
            float* fb = out + b * (MAX_DET * 4) + tid * 4;
            float* fs = out + B_IMG * MAX_DET * 4 + b * MAX_DET + tid;
            float* fl = out + B_IMG * MAX_DET * 4 + B_IMG * MAX_DET + b * MAX_DET + tid;
            if (tid < Ncoll) {
                unsigned long long kk = s_key[tid];
                unsigned u = (unsigned)(kk >> 16);
                int flat = 0xFFFF - (int)(kk & 0xFFFF);
                int c = flat / MAX_DET, r = flat % MAX_DET;
                int n = g_keep_idx[(b * C_CLS + c) * MAX_DET + r];
                float4 bb = reinterpret_cast<const float4*>(boxes)[b * N_BOX + n];
                fb[0] = bb.x; fb[1] = bb.y; fb[2] = bb.z; fb[3] = bb.w;
                *fs = __uint_as_float(u);
                *fl = (float)c;
            } else {
                fb[0] = -1.0f; fb[1] = -1.0f; fb[2] = -1.0f; fb[3] = -1.0f;
                *fs = -1.0f; *fl = -1.0f;
            }
        }

        // reset barrier-2 counter for next replay (all spinners released
        // ~20us ago; spin observation latency is ~300 cycles)
        __syncthreads();
        if (tid == 0 && b == 0) {
            __threadfence();
            g_b2 = 0;
        }
    }
}

// ---------------- host launcher ----------------
extern "C" void kernel_launch(void* const* d_in, const int* in_sizes, int n_in,
                              void* d_out, int out_size) {
    const float* boxes = (const float*)d_in[0];           // [2,20000,4]
    const float* cls   = (const float*)d_in[1];           // [2,20000,80]
    const float* cen   = (const float*)d_in[2];           // [2,20000,1]
    float* out = (float*)d_out;                           // fb(2400) | fs(600) | fl(600)

    cudaFuncSetAttribute(fused_kernel,
                         cudaFuncAttributeMaxDynamicSharedMemorySize, SMEM_BYTES);

    fused_kernel<<<GRID, TPB, SMEM_BYTES>>>(boxes, (const float4*)cls, cen, out);
}